// round 8
// baseline (speedup 1.0000x reference)
#include <cuda_runtime.h>
#include <cuda_bf16.h>
#include <math.h>

#define LDOC 200
#define HDIM 384
#define EDIM 768
#define NBLK 128
#define NTHR 384
#define SROW 289                         // float4 per staged row (288 data + 1 pad)
#define SMEM_BYTES (32 * SROW * 16)      // 147,968 bytes

// Persistent device state. g_bar is a monotonic barrier counter: never reset,
// so it is safe across CUDA-graph replays (each launch adds exactly 202*NBLK).
__device__ __align__(16) float g_h[2][4][64][HDIM];   // [parity][cell][row][j]
__device__ unsigned long long g_bar;

__device__ __forceinline__ void grid_barrier() {
    __threadfence();                     // make this thread's stores visible (L2)
    __syncthreads();
    if (threadIdx.x == 0) {
        unsigned long long old = atomicAdd(&g_bar, 1ULL);
        unsigned long long tgt = (old / (unsigned long long)NBLK + 1ULL) * (unsigned long long)NBLK;
        while (*((volatile unsigned long long*)&g_bar) < tgt) {
            __nanosleep(64);
        }
        __threadfence();
    }
    __syncthreads();
}

__device__ __forceinline__ void fma4(float& a, const float4 x, const float4 w) {
    a = fmaf(x.x, w.x, a);
    a = fmaf(x.y, w.y, a);
    a = fmaf(x.z, w.z, a);
    a = fmaf(x.w, w.w, a);
}

__device__ __forceinline__ float sigm(float v) { return 1.0f / (1.0f + expf(-v)); }

__global__ __launch_bounds__(NTHR, 1)
void lstm_persistent(const int*   __restrict__ contexts,   // [64][200]
                     const int*   __restrict__ positions,  // [64]
                     const float* __restrict__ W_emb,      // [50000][768]
                     const float* __restrict__ W_ih,       // [4][1536][768]
                     const float* __restrict__ W_hh,       // [4][1536][384]
                     const float* __restrict__ b_lstm,     // [4][1536]
                     const float* __restrict__ W_cls,      // [2][768]
                     const float* __restrict__ b_cls,      // [2]
                     float*       __restrict__ out)        // logits[128] | probs[128] | target[64*768]
{
    extern __shared__ float4 sm[];
    const int tid  = threadIdx.x;
    const int bid  = blockIdx.x;
    const int cell = bid >> 5;           // 0..3  (0,1 = layer0; 2,3 = layer1)
    const int rh   = (bid >> 4) & 1;     // row half: rows [rh*32, rh*32+32)
    const int js   = bid & 15;           // j slice: 24 j's
    const int j0   = js * 24;
    const int w    = tid >> 5;           // warp 0..11
    const int lane = tid & 31;
    const int row  = rh * 32 + lane;
    const int jA   = j0 + w;
    const int jB   = j0 + 12 + w;
    const bool isL1 = (cell >= 2);

    // ---- zero h state (both parities) ----
    {
        float4 z = make_float4(0.f, 0.f, 0.f, 0.f);
        float4* hp = (float4*)g_h;
        const int n4 = 2 * 4 * 64 * HDIM / 4;   // 49152
        for (int i = bid * NTHR + tid; i < n4; i += NBLK * NTHR) hp[i] = z;
    }
    grid_barrier();

    // cell state in registers (this thread owns (cell,row,jA/jB) forever)
    float cA = 0.f, cB = 0.f;
    const int pos = __ldg(&positions[row]);
    float* tgt = out + 256;

    const float4* WihA = (const float4*)(W_ih + ((size_t)cell * 1536 + jA) * EDIM);
    const float4* WihB = (const float4*)(W_ih + ((size_t)cell * 1536 + jB) * EDIM);
    const float4* WhhA = (const float4*)(W_hh + ((size_t)cell * 1536 + jA) * HDIM);
    const float4* WhhB = (const float4*)(W_hh + ((size_t)cell * 1536 + jB) * HDIM);
    const int GI = 384 * EDIM / 4;   // gate stride in W_ih, float4 units (73728)
    const int GH = 384 * HDIM / 4;   // gate stride in W_hh, float4 units (36864)
    const float* bb = b_lstm + cell * 1536;

    // Pipelined phases: layer0 computes step t=p while layer1 computes step t=p-1.
    // All reads from parity (p-1)&1, all writes to parity p&1.
    for (int p = 0; p <= LDOC; p++) {
        const int par_w = p & 1;
        const int par_r = par_w ^ 1;
        const int t = isL1 ? (p - 1) : p;
        const bool active = isL1 ? (p >= 1) : (p < LDOC);

        if (active) {
            // ---- stage input [32 rows][288 float4] into SMEM ----
            for (int idx = tid; idx < 32 * 288; idx += NTHR) {
                const int r = idx / 288;
                const int q = idx - r * 288;
                const int srow = rh * 32 + r;
                float4 v;
                if (q < 192) {
                    if (!isL1) {
                        const int tok = __ldg(&contexts[srow * LDOC + t]);
                        v = __ldg((const float4*)(W_emb + (size_t)tok * EDIM) + q);
                    } else {
                        const int half = (q >= 96) ? 1 : 0;
                        v = __ldcg((const float4*)(&g_h[par_r][half][srow][0]) + (q - 96 * half));
                    }
                } else {
                    v = __ldcg((const float4*)(&g_h[par_r][cell][srow][0]) + (q - 192));
                }
                sm[r * SROW + q] = v;
            }
            __syncthreads();

            // ---- accumulate gates for (row, jA) and (row, jB) ----
            float aiA = __ldg(bb + jA),        afA = __ldg(bb + 384 + jA);
            float agA = __ldg(bb + 768 + jA),  aoA = __ldg(bb + 1152 + jA);
            float aiB = __ldg(bb + jB),        afB = __ldg(bb + 384 + jB);
            float agB = __ldg(bb + 768 + jB),  aoB = __ldg(bb + 1152 + jB);

            const float4* xr = sm + lane * SROW;

            #pragma unroll 2
            for (int q = 0; q < 192; q++) {            // input projection (K=768)
                const float4 x = xr[q];
                fma4(aiA, x, __ldg(WihA + q));
                fma4(afA, x, __ldg(WihA + GI + q));
                fma4(agA, x, __ldg(WihA + 2 * GI + q));
                fma4(aoA, x, __ldg(WihA + 3 * GI + q));
                fma4(aiB, x, __ldg(WihB + q));
                fma4(afB, x, __ldg(WihB + GI + q));
                fma4(agB, x, __ldg(WihB + 2 * GI + q));
                fma4(aoB, x, __ldg(WihB + 3 * GI + q));
            }
            #pragma unroll 2
            for (int q = 0; q < 96; q++) {             // hidden projection (K=384)
                const float4 x = xr[192 + q];
                fma4(aiA, x, __ldg(WhhA + q));
                fma4(afA, x, __ldg(WhhA + GH + q));
                fma4(agA, x, __ldg(WhhA + 2 * GH + q));
                fma4(aoA, x, __ldg(WhhA + 3 * GH + q));
                fma4(aiB, x, __ldg(WhhB + q));
                fma4(afB, x, __ldg(WhhB + GH + q));
                fma4(agB, x, __ldg(WhhB + 2 * GH + q));
                fma4(aoB, x, __ldg(WhhB + 3 * GH + q));
            }

            // ---- activations + state update ----
            cA = sigm(afA) * cA + sigm(aiA) * tanhf(agA);
            const float hA = sigm(aoA) * tanhf(cA);
            cB = sigm(afB) * cB + sigm(aiB) * tanhf(agB);
            const float hB = sigm(aoB) * tanhf(cB);

            __stcg(&g_h[par_w][cell][row][jA], hA);
            __stcg(&g_h[par_w][cell][row][jB], hB);

            if (isL1 && t == pos) {
                __stcg(&tgt[row * 768 + (cell - 2) * 384 + jA], hA);
                __stcg(&tgt[row * 768 + (cell - 2) * 384 + jB], hB);
            }
        }
        grid_barrier();
    }

    // ---- classifier head: logits / probs from the gathered target reps ----
    if (bid == 0 && tid < 128) {
        const int b = tid >> 1;
        const int c = tid & 1;
        const float4* tv = (const float4*)(tgt + b * 768);
        const float4* wv = (const float4*)(W_cls + c * 768);
        float acc = __ldg(&b_cls[c]);
        #pragma unroll 4
        for (int q = 0; q < 192; q++) {
            const float4 x = __ldcg(tv + q);
            const float4 ww = __ldg(wv + q);
            acc = fmaf(x.x, ww.x, acc);
            acc = fmaf(x.y, ww.y, acc);
            acc = fmaf(x.z, ww.z, acc);
            acc = fmaf(x.w, ww.w, acc);
        }
        out[tid] = acc;                              // logits [64][2]
        out[128 + tid] = 1.0f / (1.0f + expf(-acc)); // probs  [64][2]
    }
}

extern "C" void kernel_launch(void* const* d_in, const int* in_sizes, int n_in,
                              void* d_out, int out_size) {
    (void)in_sizes; (void)n_in; (void)out_size;
    // Idempotent attribute set (not a stream op; safe under graph capture).
    cudaFuncSetAttribute(lstm_persistent, cudaFuncAttributeMaxDynamicSharedMemorySize, SMEM_BYTES);
    lstm_persistent<<<NBLK, NTHR, SMEM_BYTES>>>(
        (const int*)d_in[0],     // contexts
        (const int*)d_in[1],     // positions
        (const float*)d_in[2],   // W_emb
        (const float*)d_in[3],   // W_ih
        (const float*)d_in[4],   // W_hh
        (const float*)d_in[5],   // b_lstm
        (const float*)d_in[6],   // W_cls
        (const float*)d_in[7],   // b_cls
        (float*)d_out);
}

// round 9
// speedup vs baseline: 1.0031x; 1.0031x over previous
#include <cuda_runtime.h>
#include <cuda_bf16.h>
#include <math.h>

#define LDOC 200
#define HDIM 384
#define EDIM 768
#define NBLK 128
#define NTHR 384
#define SROW 289                         // float4 per staged row (288 data + 1 pad)
#define SMEM_BYTES (32 * SROW * 16)      // 147,968 bytes

// Persistent device state. g_bar is a monotonic barrier counter: never reset,
// so it is safe across CUDA-graph replays (each launch adds exactly 202*NBLK).
__device__ __align__(16) float g_h[2][4][64][HDIM];   // [parity][cell][row][j]
__device__ unsigned long long g_bar;

__device__ __forceinline__ void grid_barrier() {
    __threadfence();                     // make this thread's stores visible (L2)
    __syncthreads();
    if (threadIdx.x == 0) {
        unsigned long long old = atomicAdd(&g_bar, 1ULL);
        unsigned long long tgt = (old / (unsigned long long)NBLK + 1ULL) * (unsigned long long)NBLK;
        while (*((volatile unsigned long long*)&g_bar) < tgt) {
            __nanosleep(64);
        }
        __threadfence();
    }
    __syncthreads();
}

__device__ __forceinline__ void fma4(float& a, const float4 x, const float4 w) {
    a = fmaf(x.x, w.x, a);
    a = fmaf(x.y, w.y, a);
    a = fmaf(x.z, w.z, a);
    a = fmaf(x.w, w.w, a);
}

__device__ __forceinline__ float sigm(float v) { return 1.0f / (1.0f + expf(-v)); }

__global__ __launch_bounds__(NTHR, 1)
void lstm_persistent(const int*   __restrict__ contexts,   // [64][200]
                     const int*   __restrict__ positions,  // [64]
                     const float* __restrict__ W_emb,      // [50000][768]
                     const float* __restrict__ W_ih,       // [4][1536][768]
                     const float* __restrict__ W_hh,       // [4][1536][384]
                     const float* __restrict__ b_lstm,     // [4][1536]
                     const float* __restrict__ W_cls,      // [2][768]
                     const float* __restrict__ b_cls,      // [2]
                     float*       __restrict__ out)        // logits[128] | probs[128] | target[64*768]
{
    extern __shared__ float4 sm[];
    const int tid  = threadIdx.x;
    const int bid  = blockIdx.x;
    const int cell = bid >> 5;           // 0..3  (0,1 = layer0; 2,3 = layer1)
    const int rh   = (bid >> 4) & 1;     // row half: rows [rh*32, rh*32+32)
    const int js   = bid & 15;           // j slice: 24 j's
    const int j0   = js * 24;
    const int w    = tid >> 5;           // warp 0..11
    const int lane = tid & 31;
    const int row  = rh * 32 + lane;
    const int jA   = j0 + w;
    const int jB   = j0 + 12 + w;
    const bool isL1 = (cell >= 2);

    // ---- zero h state (both parities) ----
    {
        float4 z = make_float4(0.f, 0.f, 0.f, 0.f);
        float4* hp = (float4*)g_h;
        const int n4 = 2 * 4 * 64 * HDIM / 4;   // 49152
        for (int i = bid * NTHR + tid; i < n4; i += NBLK * NTHR) hp[i] = z;
    }
    grid_barrier();

    // cell state in registers (this thread owns (cell,row,jA/jB) forever)
    float cA = 0.f, cB = 0.f;
    const int pos = __ldg(&positions[row]);
    float* tgt = out + 256;

    const float4* WihA = (const float4*)(W_ih + ((size_t)cell * 1536 + jA) * EDIM);
    const float4* WihB = (const float4*)(W_ih + ((size_t)cell * 1536 + jB) * EDIM);
    const float4* WhhA = (const float4*)(W_hh + ((size_t)cell * 1536 + jA) * HDIM);
    const float4* WhhB = (const float4*)(W_hh + ((size_t)cell * 1536 + jB) * HDIM);
    const int GI = 384 * EDIM / 4;   // gate stride in W_ih, float4 units (73728)
    const int GH = 384 * HDIM / 4;   // gate stride in W_hh, float4 units (36864)
    const float* bb = b_lstm + cell * 1536;

    // Pipelined phases: layer0 computes step t=p while layer1 computes step t=p-1.
    // All reads from parity (p-1)&1, all writes to parity p&1.
    for (int p = 0; p <= LDOC; p++) {
        const int par_w = p & 1;
        const int par_r = par_w ^ 1;
        const int t = isL1 ? (p - 1) : p;
        const bool active = isL1 ? (p >= 1) : (p < LDOC);

        if (active) {
            // ---- stage input [32 rows][288 float4] into SMEM ----
            for (int idx = tid; idx < 32 * 288; idx += NTHR) {
                const int r = idx / 288;
                const int q = idx - r * 288;
                const int srow = rh * 32 + r;
                float4 v;
                if (q < 192) {
                    if (!isL1) {
                        const int tok = __ldg(&contexts[srow * LDOC + t]);
                        v = __ldg((const float4*)(W_emb + (size_t)tok * EDIM) + q);
                    } else {
                        const int half = (q >= 96) ? 1 : 0;
                        v = __ldcg((const float4*)(&g_h[par_r][half][srow][0]) + (q - 96 * half));
                    }
                } else {
                    v = __ldcg((const float4*)(&g_h[par_r][cell][srow][0]) + (q - 192));
                }
                sm[r * SROW + q] = v;
            }
            __syncthreads();

            // ---- accumulate gates for (row, jA) and (row, jB) ----
            float aiA = __ldg(bb + jA),        afA = __ldg(bb + 384 + jA);
            float agA = __ldg(bb + 768 + jA),  aoA = __ldg(bb + 1152 + jA);
            float aiB = __ldg(bb + jB),        afB = __ldg(bb + 384 + jB);
            float agB = __ldg(bb + 768 + jB),  aoB = __ldg(bb + 1152 + jB);

            const float4* xr = sm + lane * SROW;

            #pragma unroll 2
            for (int q = 0; q < 192; q++) {            // input projection (K=768)
                const float4 x = xr[q];
                fma4(aiA, x, __ldg(WihA + q));
                fma4(afA, x, __ldg(WihA + GI + q));
                fma4(agA, x, __ldg(WihA + 2 * GI + q));
                fma4(aoA, x, __ldg(WihA + 3 * GI + q));
                fma4(aiB, x, __ldg(WihB + q));
                fma4(afB, x, __ldg(WihB + GI + q));
                fma4(agB, x, __ldg(WihB + 2 * GI + q));
                fma4(aoB, x, __ldg(WihB + 3 * GI + q));
            }
            #pragma unroll 2
            for (int q = 0; q < 96; q++) {             // hidden projection (K=384)
                const float4 x = xr[192 + q];
                fma4(aiA, x, __ldg(WhhA + q));
                fma4(afA, x, __ldg(WhhA + GH + q));
                fma4(agA, x, __ldg(WhhA + 2 * GH + q));
                fma4(aoA, x, __ldg(WhhA + 3 * GH + q));
                fma4(aiB, x, __ldg(WhhB + q));
                fma4(afB, x, __ldg(WhhB + GH + q));
                fma4(agB, x, __ldg(WhhB + 2 * GH + q));
                fma4(aoB, x, __ldg(WhhB + 3 * GH + q));
            }

            // ---- activations + state update ----
            cA = sigm(afA) * cA + sigm(aiA) * tanhf(agA);
            const float hA = sigm(aoA) * tanhf(cA);
            cB = sigm(afB) * cB + sigm(aiB) * tanhf(agB);
            const float hB = sigm(aoB) * tanhf(cB);

            __stcg(&g_h[par_w][cell][row][jA], hA);
            __stcg(&g_h[par_w][cell][row][jB], hB);

            if (isL1 && t == pos) {
                __stcg(&tgt[row * 768 + (cell - 2) * 384 + jA], hA);
                __stcg(&tgt[row * 768 + (cell - 2) * 384 + jB], hB);
            }
        }
        grid_barrier();
    }

    // ---- classifier head: logits / probs from the gathered target reps ----
    if (bid == 0 && tid < 128) {
        const int b = tid >> 1;
        const int c = tid & 1;
        const float4* tv = (const float4*)(tgt + b * 768);
        const float4* wv = (const float4*)(W_cls + c * 768);
        float acc = __ldg(&b_cls[c]);
        #pragma unroll 4
        for (int q = 0; q < 192; q++) {
            const float4 x = __ldcg(tv + q);
            const float4 ww = __ldg(wv + q);
            acc = fmaf(x.x, ww.x, acc);
            acc = fmaf(x.y, ww.y, acc);
            acc = fmaf(x.z, ww.z, acc);
            acc = fmaf(x.w, ww.w, acc);
        }
        out[tid] = acc;                              // logits [64][2]
        out[128 + tid] = 1.0f / (1.0f + expf(-acc)); // probs  [64][2]
    }
}

extern "C" void kernel_launch(void* const* d_in, const int* in_sizes, int n_in,
                              void* d_out, int out_size) {
    (void)in_sizes; (void)n_in; (void)out_size;
    // Idempotent attribute set (not a stream op; safe under graph capture).
    cudaFuncSetAttribute(lstm_persistent, cudaFuncAttributeMaxDynamicSharedMemorySize, SMEM_BYTES);
    lstm_persistent<<<NBLK, NTHR, SMEM_BYTES>>>(
        (const int*)d_in[0],     // contexts
        (const int*)d_in[1],     // positions
        (const float*)d_in[2],   // W_emb
        (const float*)d_in[3],   // W_ih
        (const float*)d_in[4],   // W_hh
        (const float*)d_in[5],   // b_lstm
        (const float*)d_in[6],   // W_cls
        (const float*)d_in[7],   // b_cls
        (float*)d_out);
}